// round 15
// baseline (speedup 1.0000x reference)
#include <cuda_runtime.h>
#include <cuda_fp16.h>
#include <math.h>
#include <stdint.h>

// Problem constants
#define BATCH 2
#define SEQ   2048
#define DMODEL 1024
#define NHEAD 16
#define DHEAD 64
#define MTOT  (BATCH*SEQ)      // 4096
#define NQKV  (5*DMODEL)       // 5120 (q0,q1,k0,k1,v concatenated)
#define LAMBDA_INIT 0.8f
#define LN_EPS 1e-5f
#define LOG2E 1.44269504088896340736f

// ---------------------------------------------------------------------------
// Scratch
// ---------------------------------------------------------------------------
__device__ __half g_qkvh[MTOT*NQKV];        // merged projection output
__device__ __half g_xh[MTOT*DMODEL];
__device__ __half g_attnh[MTOT*DMODEL];
__device__ __half g_wcat[DMODEL*NQKV];      // concatenated weights
__device__ __half g_woh[DMODEL*DMODEL];
__device__ float g_lambda;

// ---------------------------------------------------------------------------
// Fused preamble (R13-measured): X->fp16, 5 weights packed, WO->fp16, lambda.
// ---------------------------------------------------------------------------
__global__ void convert_all_kernel(
        const float* __restrict__ inp,
        const float* __restrict__ wq0, const float* __restrict__ wq1,
        const float* __restrict__ wk0, const float* __restrict__ wk1,
        const float* __restrict__ wv,  const float* __restrict__ wo,
        const float* __restrict__ l0,  const float* __restrict__ l1,
        const float* __restrict__ l2,  const float* __restrict__ l3,
        __half* __restrict__ xh, __half* __restrict__ wcat,
        __half* __restrict__ woh) {
    int blk = blockIdx.x;
    int tid = threadIdx.x;

    if (blk < 4096) {
        int i = blk * 1024 + tid * 4;
        float4 v = *(const float4*)(inp + i);
        *(__half2*)(xh + i)     = __floats2half2_rn(v.x, v.y);
        *(__half2*)(xh + i + 2) = __floats2half2_rn(v.z, v.w);
    } else if (blk < 9216) {
        int r = blk - 4096;
        int wi = r >> 10;
        const float* src;
        switch (wi) {
            case 0: src = wq0; break;
            case 1: src = wq1; break;
            case 2: src = wk0; break;
            case 3: src = wk1; break;
            default: src = wv; break;
        }
        int i = (r & 1023) * 1024 + tid * 4;
        int k = i >> 10;
        int n = i & 1023;
        float4 v = *(const float4*)(src + i);
        __half* dst = wcat + (size_t)k * NQKV + wi * DMODEL + n;
        *(__half2*)(dst)     = __floats2half2_rn(v.x, v.y);
        *(__half2*)(dst + 2) = __floats2half2_rn(v.z, v.w);
    } else if (blk < 10240) {
        int i = (blk - 9216) * 1024 + tid * 4;
        float4 v = *(const float4*)(wo + i);
        *(__half2*)(woh + i)     = __floats2half2_rn(v.x, v.y);
        *(__half2*)(woh + i + 2) = __floats2half2_rn(v.z, v.w);
    } else {
        if (tid < 32) {
            float a = l0[tid]*l1[tid] + l0[tid+32]*l1[tid+32];
            float b = l2[tid]*l3[tid] + l2[tid+32]*l3[tid+32];
            #pragma unroll
            for (int o = 16; o >= 1; o >>= 1) {
                a += __shfl_xor_sync(0xffffffffu, a, o);
                b += __shfl_xor_sync(0xffffffffu, b, o);
            }
            if (tid == 0)
                g_lambda = (-expf(a) + LAMBDA_INIT) + (-expf(b) + LAMBDA_INIT);
        }
    }
}

__device__ __forceinline__ float ex2f(float x) {
    float r;
    asm("ex2.approx.f32 %0, %1;" : "=f"(r) : "f"(x));
    return r;
}
__device__ __forceinline__ uint32_t packh2(float lo, float hi) {
    __half2 h = __floats2half2_rn(lo, hi);
    return *(uint32_t*)&h;
}

// ---------------------------------------------------------------------------
// FP16 tensor-core GEMM (R13-measured): 3-stage cp.async pipeline.
// ---------------------------------------------------------------------------
#define HBM 128
#define HBN 128
#define HBK 64
#define A_LDH 72
#define B_LDH 136
#define HAS_STAGE (HBM*A_LDH)
#define HBS_STAGE (HBK*B_LDH)
#define GSTAGES 3
#define HGEMM_SMEM_BYTES ((GSTAGES*(HAS_STAGE+HBS_STAGE))*2)   // 107520

template <typename CT>
__global__ __launch_bounds__(256, 2) void gemm_f16(const __half* __restrict__ A,
                                                   const __half* __restrict__ B,
                                                   CT* __restrict__ C,
                                                   int M, int N, int K) {
    extern __shared__ __align__(16) char smraw[];
    __half* As = (__half*)smraw;
    __half* Bs = As + GSTAGES * HAS_STAGE;

    int tid  = threadIdx.x;
    int lane = tid & 31;
    int warp = tid >> 5;
    int g    = lane >> 2;
    int tig  = lane & 3;
    int wm   = (warp >> 2) * 64;
    int wn   = (warp & 3) * 32;

    int bx = blockIdx.x, by = blockIdx.y;

    const __half* Ag = A + (size_t)(by * HBM) * K;
    const __half* Bg = B + bx * HBN;

    uint32_t s_as = (uint32_t)__cvta_generic_to_shared(As);
    uint32_t s_bs = (uint32_t)__cvta_generic_to_shared(Bs);

    float acc[4][4][4];
    #pragma unroll
    for (int i = 0; i < 4; i++)
        #pragma unroll
        for (int j = 0; j < 4; j++)
            #pragma unroll
            for (int q = 0; q < 4; q++) acc[i][j][q] = 0.f;

    uint32_t a_lane = ((uint32_t)((wm + (lane & 15)) * A_LDH + (lane >> 4) * 8)) * 2u;
    uint32_t b_lane = ((uint32_t)((lane & 15) * B_LDH + wn + (lane >> 4) * 8)) * 2u;

    const int NT = K / HBK;

    auto prefetch = [&](int kt, int stage) {
        uint32_t ad = s_as + (uint32_t)(stage * HAS_STAGE) * 2u;
        uint32_t bd = s_bs + (uint32_t)(stage * HBS_STAGE) * 2u;
        const __half* agk = Ag + kt * HBK;
        const __half* bgk = Bg + (size_t)(kt * HBK) * N;
        #pragma unroll
        for (int r = 0; r < 4; r++) {
            int c = tid + r * 256;
            int arow = c >> 3, acol = (c & 7) * 8;
            asm volatile("cp.async.cg.shared.global [%0], [%1], 16;\n"
                         :: "r"(ad + (uint32_t)(arow * A_LDH + acol) * 2u),
                            "l"(agk + (size_t)arow * K + acol));
            int brow = c >> 4, bcol = (c & 15) * 8;
            asm volatile("cp.async.cg.shared.global [%0], [%1], 16;\n"
                         :: "r"(bd + (uint32_t)(brow * B_LDH + bcol) * 2u),
                            "l"(bgk + (size_t)brow * N + bcol));
        }
        asm volatile("cp.async.commit_group;\n");
    };

    prefetch(0, 0);
    prefetch(1, 1);

    int cs = 0;
    int ps = 2;

    for (int kt = 0; kt < NT; kt++) {
        asm volatile("cp.async.wait_group 1;\n");
        __syncthreads();
        if (kt + 2 < NT) prefetch(kt + 2, ps);
        else asm volatile("cp.async.commit_group;\n");

        uint32_t a_base = s_as + (uint32_t)(cs * HAS_STAGE) * 2u + a_lane;
        uint32_t b_base = s_bs + (uint32_t)(cs * HBS_STAGE) * 2u + b_lane;

        #pragma unroll
        for (int k16 = 0; k16 < HBK / 16; k16++) {
            uint32_t a[4][4];
            #pragma unroll
            for (int i = 0; i < 4; i++) {
                uint32_t addr = a_base + (uint32_t)(i * 16 * A_LDH + k16 * 16) * 2u;
                asm volatile("ldmatrix.sync.aligned.m8n8.x4.shared.b16 {%0,%1,%2,%3}, [%4];\n"
                             : "=r"(a[i][0]), "=r"(a[i][1]), "=r"(a[i][2]), "=r"(a[i][3])
                             : "r"(addr));
            }
            uint32_t bf[4][2];
            #pragma unroll
            for (int jp = 0; jp < 2; jp++) {
                uint32_t addr = b_base + (uint32_t)(k16 * 16 * B_LDH + jp * 16) * 2u;
                asm volatile("ldmatrix.sync.aligned.m8n8.x4.trans.shared.b16 {%0,%1,%2,%3}, [%4];\n"
                             : "=r"(bf[2*jp][0]), "=r"(bf[2*jp][1]),
                               "=r"(bf[2*jp+1][0]), "=r"(bf[2*jp+1][1])
                             : "r"(addr));
            }
            #pragma unroll
            for (int i = 0; i < 4; i++)
                #pragma unroll
                for (int j = 0; j < 4; j++)
                    asm volatile(
                        "mma.sync.aligned.m16n8k16.row.col.f32.f16.f16.f32 "
                        "{%0,%1,%2,%3}, {%4,%5,%6,%7}, {%8,%9}, {%0,%1,%2,%3};\n"
                        : "+f"(acc[i][j][0]), "+f"(acc[i][j][1]),
                          "+f"(acc[i][j][2]), "+f"(acc[i][j][3])
                        : "r"(a[i][0]), "r"(a[i][1]), "r"(a[i][2]), "r"(a[i][3]),
                          "r"(bf[j][0]), "r"(bf[j][1]));
        }
        cs = (cs == GSTAGES - 1) ? 0 : cs + 1;
        ps = (ps == GSTAGES - 1) ? 0 : ps + 1;
    }

    #pragma unroll
    for (int i = 0; i < 4; i++) {
        int row = by * HBM + wm + i * 16 + g;
        #pragma unroll
        for (int j = 0; j < 4; j++) {
            int col = bx * HBN + wn + j * 8 + 2 * tig;
            if (sizeof(CT) == 4) {
                *(float2*)((float*)C + (size_t)row * N + col) =
                    make_float2(acc[i][j][0], acc[i][j][1]);
                *(float2*)((float*)C + (size_t)(row + 8) * N + col) =
                    make_float2(acc[i][j][2], acc[i][j][3]);
            } else {
                *(__half2*)((__half*)C + (size_t)row * N + col) =
                    __floats2half2_rn(acc[i][j][0], acc[i][j][1]);
                *(__half2*)((__half*)C + (size_t)(row + 8) * N + col) =
                    __floats2half2_rn(acc[i][j][2], acc[i][j][3]);
            }
        }
    }
}

// ---------------------------------------------------------------------------
// FP16 tensor-core differential flash attention + per-head LayerNorm.
// NEW: P stays in registers — the QK accumulator fragment layout IS the PV
// A-operand fragment layout (a0/a1 = rows g/g+8, a2/a3 = +8 col offset).
// No sP buffer, no P ldmatrix, no syncwarps.
// ---------------------------------------------------------------------------
#define QT 128
#define QLDH 72
#define KLDH 72
#define VLDH 72
#define KH_STAGE (64*KLDH)
#define VH_STAGE (64*VLDH)
#define SQH_OFF  0
#define SK0H_OFF (2*QT*QLDH)
#define SK1H_OFF (SK0H_OFF + 2*KH_STAGE)
#define SVH_OFF  (SK1H_OFF + 2*KH_STAGE)
#define ATTN3_SMEM_HALVES (SVH_OFF + 2*VH_STAGE)   // 46080
#define ATTN3_SMEM_BYTES (ATTN3_SMEM_HALVES*2)     // 92160

__global__ __launch_bounds__(256, 2) void attn_tc_kernel(
        const __half* __restrict__ qkv,
        const float* __restrict__ ln_w, const float* __restrict__ ln_b,
        __half* __restrict__ attnh) {
    extern __shared__ __align__(16) char smraw[];
    __half* smh = (__half*)smraw;
    __half* sQ  = smh + SQH_OFF;
    __half* sK0 = smh + SK0H_OFF;
    __half* sK1 = smh + SK1H_OFF;
    __half* sV  = smh + SVH_OFF;

    int qt = gridDim.x - 1 - blockIdx.x;   // heavy tiles first
    int bh = blockIdx.y;
    int b = bh >> 4, h = bh & 15;

    int tid = threadIdx.x;
    int lane = tid & 31;
    int w = tid >> 5;
    int g = lane >> 2;
    int tig = lane & 3;

    const float scale2 = 0.125f * LOG2E;
    const float slope2 = exp2f(-0.5f * (float)(h + 1)) * LOG2E;
    const size_t basec = (size_t)b * SEQ * NQKV + (size_t)h * DHEAD;

    uint32_t s_q  = (uint32_t)__cvta_generic_to_shared(sQ);
    uint32_t s_k0 = (uint32_t)__cvta_generic_to_shared(sK0);
    uint32_t s_k1 = (uint32_t)__cvta_generic_to_shared(sK1);
    uint32_t s_v  = (uint32_t)__cvta_generic_to_shared(sV);

    // --- load Q (both streams) via cp.async ---
    {
        int row = tid >> 1;
        int c0  = (tid & 1) * 32;
        size_t gofs = basec + (size_t)(qt * QT + row) * NQKV + c0;
        #pragma unroll
        for (int st = 0; st < 2; st++) {
            const __half* src = qkv + gofs + st * DMODEL;
            uint32_t dst = s_q + (uint32_t)(st * QT * QLDH + row * QLDH + c0) * 2u;
            #pragma unroll
            for (int c = 0; c < 32; c += 8)
                asm volatile("cp.async.cg.shared.global [%0], [%1], 16;\n"
                             :: "r"(dst + c * 2u), "l"(src + c));
        }
        asm volatile("cp.async.commit_group;\n");
    }

    float oacc[2][8][4];
    #pragma unroll
    for (int st = 0; st < 2; st++)
        #pragma unroll
        for (int j = 0; j < 8; j++)
            #pragma unroll
            for (int q = 0; q < 4; q++) oacc[st][j][q] = 0.f;
    float mrow[2][2], lrow[2][2];
    #pragma unroll
    for (int st = 0; st < 2; st++)
        #pragma unroll
        for (int hh = 0; hh < 2; hh++) { mrow[st][hh] = -INFINITY; lrow[st][hh] = 0.f; }

    uint32_t qa_lane = ((uint32_t)((w * 16 + (lane & 15)) * QLDH + (lane >> 4) * 8)) * 2u;
    uint32_t kb_lane = ((uint32_t)(((lane & 7) + ((lane >> 4) & 1) * 8) * KLDH
                                   + ((lane >> 3) & 1) * 8)) * 2u;
    uint32_t vb_lane = ((uint32_t)((lane & 15) * VLDH + (lane >> 4) * 8)) * 2u;

    const int qrow0 = qt * QT + w * 16;
    const int qq0 = qrow0 + g;

    const int prow = tid >> 2;
    const int pc0  = (tid & 3) * 16;

    auto prefetch = [&](int kt, int stage) {
        size_t gofs = basec + (size_t)(kt * 64 + prow) * NQKV + pc0;
        const __half* gk0 = qkv + gofs + 2 * DMODEL;
        const __half* gk1 = qkv + gofs + 3 * DMODEL;
        const __half* gv  = qkv + gofs + 4 * DMODEL;
        uint32_t dk0 = s_k0 + (uint32_t)(stage * KH_STAGE + prow * KLDH + pc0) * 2u;
        uint32_t dk1 = s_k1 + (uint32_t)(stage * KH_STAGE + prow * KLDH + pc0) * 2u;
        uint32_t dv  = s_v  + (uint32_t)(stage * VH_STAGE + prow * VLDH + pc0) * 2u;
        #pragma unroll
        for (int c = 0; c < 16; c += 8) {
            asm volatile("cp.async.cg.shared.global [%0], [%1], 16;\n"
                         :: "r"(dk0 + c * 2u), "l"(gk0 + c));
            asm volatile("cp.async.cg.shared.global [%0], [%1], 16;\n"
                         :: "r"(dk1 + c * 2u), "l"(gk1 + c));
            asm volatile("cp.async.cg.shared.global [%0], [%1], 16;\n"
                         :: "r"(dv + c * 2u), "l"(gv + c));
        }
        asm volatile("cp.async.commit_group;\n");
    };

    const int ktmax = 2 * qt + 1;

    prefetch(0, 0);

    for (int kt = 0; kt <= ktmax; kt++) {
        int stage = kt & 1;
        asm volatile("cp.async.wait_group 0;\n");
        __syncthreads();
        if (kt < ktmax) prefetch(kt + 1, stage ^ 1);

        const bool active = (kt * 64 <= qrow0 + 15);
        const bool diag   = (kt * 64 + 63 > qrow0);

        if (active) {
            uint32_t kbase0 = s_k0 + (uint32_t)(stage * KH_STAGE) * 2u + kb_lane;
            uint32_t kbase1 = s_k1 + (uint32_t)(stage * KH_STAGE) * 2u + kb_lane;
            uint32_t vbase  = s_v  + (uint32_t)(stage * VH_STAGE) * 2u + vb_lane;
            const float kb = slope2 * (float)(kt * 64 + 2 * tig);

            #pragma unroll
            for (int st = 0; st < 2; st++) {
                uint32_t kbb = (st == 0) ? kbase0 : kbase1;

                float sc[8][4];
                #pragma unroll
                for (int j = 0; j < 8; j++)
                    #pragma unroll
                    for (int q = 0; q < 4; q++) sc[j][q] = 0.f;

                uint32_t qa_base = s_q + (uint32_t)(st * QT * QLDH) * 2u + qa_lane;
                #pragma unroll
                for (int k16 = 0; k16 < 4; k16++) {
                    uint32_t a0, a1, a2, a3;
                    asm volatile("ldmatrix.sync.aligned.m8n8.x4.shared.b16 {%0,%1,%2,%3}, [%4];\n"
                                 : "=r"(a0), "=r"(a1), "=r"(a2), "=r"(a3)
                                 : "r"(qa_base + (uint32_t)(k16 * 16) * 2u));
                    #pragma unroll
                    for (int jp = 0; jp < 4; jp++) {
                        uint32_t b0, b1, b2, b3;
                        uint32_t addr = kbb + (uint32_t)(jp * 16 * KLDH + k16 * 16) * 2u;
                        asm volatile("ldmatrix.sync.aligned.m8n8.x4.shared.b16 {%0,%1,%2,%3}, [%4];\n"
                                     : "=r"(b0), "=r"(b1), "=r"(b2), "=r"(b3) : "r"(addr));
                        asm volatile(
                            "mma.sync.aligned.m16n8k16.row.col.f32.f16.f16.f32 "
                            "{%0,%1,%2,%3}, {%4,%5,%6,%7}, {%8,%9}, {%0,%1,%2,%3};\n"
                            : "+f"(sc[2*jp][0]), "+f"(sc[2*jp][1]),
                              "+f"(sc[2*jp][2]), "+f"(sc[2*jp][3])
                            : "r"(a0), "r"(a1), "r"(a2), "r"(a3), "r"(b0), "r"(b1));
                        asm volatile(
                            "mma.sync.aligned.m16n8k16.row.col.f32.f16.f16.f32 "
                            "{%0,%1,%2,%3}, {%4,%5,%6,%7}, {%8,%9}, {%0,%1,%2,%3};\n"
                            : "+f"(sc[2*jp+1][0]), "+f"(sc[2*jp+1][1]),
                              "+f"(sc[2*jp+1][2]), "+f"(sc[2*jp+1][3])
                            : "r"(a0), "r"(a1), "r"(a2), "r"(a3), "r"(b2), "r"(b3));
                    }
                }

                // ---- softmax (online, log2 domain, folded bias) ----
                #pragma unroll
                for (int hh = 0; hh < 2; hh++) {
                    int qq = qq0 + hh * 8;
                    float mx = -INFINITY;
                    #pragma unroll
                    for (int j = 0; j < 8; j++) {
                        #pragma unroll
                        for (int e = 0; e < 2; e++) {
                            float s = fmaf(sc[j][hh * 2 + e], scale2,
                                           fmaf((float)(j * 8 + e), slope2, kb));
                            if (diag) {
                                int kk = kt * 64 + j * 8 + 2 * tig + e;
                                if (kk > qq) s = -INFINITY;
                            }
                            sc[j][hh * 2 + e] = s;
                            mx = fmaxf(mx, s);
                        }
                    }
                    mx = fmaxf(mx, __shfl_xor_sync(0xffffffffu, mx, 1));
                    mx = fmaxf(mx, __shfl_xor_sync(0xffffffffu, mx, 2));
                    float mn = fmaxf(mrow[st][hh], mx);
                    float corr = ex2f(mrow[st][hh] - mn);
                    mrow[st][hh] = mn;
                    float rs = 0.f;
                    #pragma unroll
                    for (int j = 0; j < 8; j++) {
                        #pragma unroll
                        for (int e = 0; e < 2; e++) {
                            float pv = ex2f(sc[j][hh * 2 + e] - mn);
                            sc[j][hh * 2 + e] = pv;
                            rs += pv;
                        }
                    }
                    rs += __shfl_xor_sync(0xffffffffu, rs, 1);
                    rs += __shfl_xor_sync(0xffffffffu, rs, 2);
                    lrow[st][hh] = lrow[st][hh] * corr + rs;
                    #pragma unroll
                    for (int j = 0; j < 8; j++) {
                        oacc[st][j][hh * 2 + 0] *= corr;
                        oacc[st][j][hh * 2 + 1] *= corr;
                    }
                }

                // ---- PV: oacc += P @ V, P fragments built IN REGISTERS ----
                // A-frag at chunk c: a0={P[g][16c+2tig],+1}, a1=rows g+8,
                //                    a2/a3 = +8 column offset (j=2c+1).
                #pragma unroll
                for (int k16 = 0; k16 < 4; k16++) {
                    uint32_t a0 = packh2(sc[2*k16][0],     sc[2*k16][1]);
                    uint32_t a1 = packh2(sc[2*k16][2],     sc[2*k16][3]);
                    uint32_t a2 = packh2(sc[2*k16+1][0],   sc[2*k16+1][1]);
                    uint32_t a3 = packh2(sc[2*k16+1][2],   sc[2*k16+1][3]);
                    #pragma unroll
                    for (int jp = 0; jp < 4; jp++) {
                        uint32_t b0, b1, b2, b3;
                        uint32_t addr = vbase + (uint32_t)(k16 * 16 * VLDH + jp * 16) * 2u;
                        asm volatile("ldmatrix.sync.aligned.m8n8.x4.trans.shared.b16 {%0,%1,%2,%3}, [%4];\n"
                                     : "=r"(b0), "=r"(b1), "=r"(b2), "=r"(b3) : "r"(addr));
                        asm volatile(
                            "mma.sync.aligned.m16n8k16.row.col.f32.f16.f16.f32 "
                            "{%0,%1,%2,%3}, {%4,%5,%6,%7}, {%8,%9}, {%0,%1,%2,%3};\n"
                            : "+f"(oacc[st][2*jp][0]), "+f"(oacc[st][2*jp][1]),
                              "+f"(oacc[st][2*jp][2]), "+f"(oacc[st][2*jp][3])
                            : "r"(a0), "r"(a1), "r"(a2), "r"(a3), "r"(b0), "r"(b1));
                        asm volatile(
                            "mma.sync.aligned.m16n8k16.row.col.f32.f16.f16.f32 "
                            "{%0,%1,%2,%3}, {%4,%5,%6,%7}, {%8,%9}, {%0,%1,%2,%3};\n"
                            : "+f"(oacc[st][2*jp+1][0]), "+f"(oacc[st][2*jp+1][1]),
                              "+f"(oacc[st][2*jp+1][2]), "+f"(oacc[st][2*jp+1][3])
                            : "r"(a0), "r"(a1), "r"(a2), "r"(a3), "r"(b2), "r"(b3));
                    }
                }
            }
        }
    }

    // --- epilogue: combine streams, per-head LayerNorm over DH, store fp16 ---
    float lam = g_lambda;
    #pragma unroll
    for (int hh = 0; hh < 2; hh++) {
        float inv0 = 1.0f / lrow[0][hh];
        float inv1 = 1.0f / lrow[1][hh];
        float o[8][2];
        float s_ = 0.f;
        #pragma unroll
        for (int j = 0; j < 8; j++) {
            #pragma unroll
            for (int e = 0; e < 2; e++) {
                float val = oacc[0][j][hh * 2 + e] * inv0
                          - lam * (oacc[1][j][hh * 2 + e] * inv1);
                o[j][e] = val;
                s_ += val;
            }
        }
        s_ += __shfl_xor_sync(0xffffffffu, s_, 1);
        s_ += __shfl_xor_sync(0xffffffffu, s_, 2);
        float mu = s_ * (1.0f / 64.0f);
        float vs = 0.f;
        #pragma unroll
        for (int j = 0; j < 8; j++) {
            #pragma unroll
            for (int e = 0; e < 2; e++) { float d = o[j][e] - mu; vs += d * d; }
        }
        vs += __shfl_xor_sync(0xffffffffu, vs, 1);
        vs += __shfl_xor_sync(0xffffffffu, vs, 2);
        float r = rsqrtf(vs * (1.0f / 64.0f) + LN_EPS);

        size_t row = (size_t)b * SEQ + (size_t)(qrow0 + g + hh * 8);
        #pragma unroll
        for (int j = 0; j < 8; j++) {
            int col = h * DHEAD + j * 8 + 2 * tig;
            float wv0 = ln_w[h * DHEAD + j * 8 + 2 * tig];
            float wv1 = ln_w[h * DHEAD + j * 8 + 2 * tig + 1];
            float bv0 = ln_b[h * DHEAD + j * 8 + 2 * tig];
            float bv1 = ln_b[h * DHEAD + j * 8 + 2 * tig + 1];
            *(__half2*)(attnh + row * DMODEL + col) =
                __floats2half2_rn((o[j][0] - mu) * r * wv0 + bv0,
                                  (o[j][1] - mu) * r * wv1 + bv1);
        }
    }
}

// ---------------------------------------------------------------------------
// Launch
// ---------------------------------------------------------------------------
extern "C" void kernel_launch(void* const* d_in, const int* in_sizes, int n_in,
                              void* d_out, int out_size) {
    const float* inp = (const float*)d_in[0];
    const float* wq0 = (const float*)d_in[1];
    const float* wq1 = (const float*)d_in[2];
    const float* wk0 = (const float*)d_in[3];
    const float* wk1 = (const float*)d_in[4];
    const float* wv  = (const float*)d_in[5];
    const float* wo  = (const float*)d_in[6];
    const float* l0  = (const float*)d_in[7];
    const float* l1  = (const float*)d_in[8];
    const float* l2  = (const float*)d_in[9];
    const float* l3  = (const float*)d_in[10];
    const float* lnw = (const float*)d_in[11];
    const float* lnb = (const float*)d_in[12];
    float* out = (float*)d_out;

    __half *qkvh, *xh, *attnh, *wcat, *woh;
    cudaGetSymbolAddress((void**)&qkvh, g_qkvh);
    cudaGetSymbolAddress((void**)&xh, g_xh);
    cudaGetSymbolAddress((void**)&attnh, g_attnh);
    cudaGetSymbolAddress((void**)&wcat, g_wcat);
    cudaGetSymbolAddress((void**)&woh, g_woh);

    cudaFuncSetAttribute(gemm_f16<float>, cudaFuncAttributeMaxDynamicSharedMemorySize,
                         HGEMM_SMEM_BYTES);
    cudaFuncSetAttribute(gemm_f16<__half>, cudaFuncAttributeMaxDynamicSharedMemorySize,
                         HGEMM_SMEM_BYTES);
    cudaFuncSetAttribute(attn_tc_kernel, cudaFuncAttributeMaxDynamicSharedMemorySize,
                         ATTN3_SMEM_BYTES);

    convert_all_kernel<<<10241, 256>>>(inp, wq0, wq1, wk0, wk1, wv, wo,
                                       l0, l1, l2, l3, xh, wcat, woh);

    dim3 pgrid(NQKV / 128, MTOT / 128);     // (40, 32) = 1280 CTAs
    gemm_f16<__half><<<pgrid, 256, HGEMM_SMEM_BYTES>>>(xh, wcat, qkvh,
                                                       MTOT, NQKV, DMODEL);

    attn_tc_kernel<<<dim3(SEQ / QT, BATCH * NHEAD), 256, ATTN3_SMEM_BYTES>>>(
        qkvh, lnw, lnb, attnh);

    dim3 ggrid(DMODEL / 128, MTOT / 128);   // (8, 32)
    gemm_f16<float><<<ggrid, 256, HGEMM_SMEM_BYTES>>>(attnh, woh, out, MTOT, DMODEL, DMODEL);
}